// round 3
// baseline (speedup 1.0000x reference)
#include <cuda_runtime.h>
#include <math_constants.h>

// TripletLoss: features [4096, 2048] f32, labels [4096] int32 -> scalar f32 loss.
// (JAX silently downgrades the reference's int64 labels to int32: x64 disabled.)
// Pipeline:
//   K1: per-row squared norms + init of per-row ap/an accumulators
//   K2: fused 128x128-tiled fp32 GEMM (X @ X^T) + distance + batch-hard
//       masked max/min epilogue committed via uint-bit atomics
//   K3: final reduction to the scalar margin-ranking loss

#define NROWS 4096
#define DDIM  2048
#define MARGIN 0.3f

__device__ float        g_sq[NROWS];
__device__ unsigned int g_ap[NROWS];   // float bits, all values >= 0
__device__ unsigned int g_an[NROWS];   // float bits, init +inf

// ---------------------------------------------------------------------------
// K1: squared norms + accumulator init. One block per row.
// ---------------------------------------------------------------------------
__global__ __launch_bounds__(256) void sq_init_kernel(const float* __restrict__ x) {
    const int row = blockIdx.x;
    const float4* xr = (const float4*)(x + (size_t)row * DDIM);
    float s = 0.f;
    #pragma unroll 2
    for (int i = threadIdx.x; i < DDIM / 4; i += 256) {
        float4 v = xr[i];
        s += v.x * v.x + v.y * v.y + v.z * v.z + v.w * v.w;
    }
    #pragma unroll
    for (int off = 16; off; off >>= 1) s += __shfl_xor_sync(0xffffffffu, s, off);
    __shared__ float ws[8];
    if ((threadIdx.x & 31) == 0) ws[threadIdx.x >> 5] = s;
    __syncthreads();
    if (threadIdx.x == 0) {
        float t = 0.f;
        #pragma unroll
        for (int w = 0; w < 8; w++) t += ws[w];
        g_sq[row] = t;
        g_ap[row] = 0u;          // 0.0f
        g_an[row] = 0x7f800000u; // +inf
    }
}

// ---------------------------------------------------------------------------
// K2: fused GEMM + batch-hard epilogue.
// 256 threads, each computes an 8x8 microtile of a 128x128 output tile.
// ---------------------------------------------------------------------------
__global__ __launch_bounds__(256, 2)
void dist_kernel(const float* __restrict__ x, const int* __restrict__ lbl) {
    __shared__ float As[16][128];
    __shared__ float Bs[16][128];
    __shared__ int lr[128], lc[128];
    __shared__ float sqr[128], sqc[128];

    const int row0 = blockIdx.y * 128;
    const int col0 = blockIdx.x * 128;
    const int tid = threadIdx.x;
    const int tx = tid & 15;   // col group (8 cols each)
    const int ty = tid >> 4;   // row group (8 rows each)

    if (tid < 128) {
        lr[tid]  = lbl[row0 + tid];
        lc[tid]  = lbl[col0 + tid];
        sqr[tid] = g_sq[row0 + tid];
        sqc[tid] = g_sq[col0 + tid];
    }

    float acc[8][8];
    #pragma unroll
    for (int i = 0; i < 8; i++)
        #pragma unroll
        for (int j = 0; j < 8; j++) acc[i][j] = 0.f;

    for (int k0 = 0; k0 < DDIM; k0 += 16) {
        __syncthreads();
        // Load 128x16 A-tile and B-tile, stored k-major for the compute phase.
        #pragma unroll
        for (int u0 = 0; u0 < 2; u0++) {
            int u  = tid + u0 * 256;     // 0..511 float4 slots
            int r  = u >> 2;             // row within tile 0..127
            int kk = (u & 3) * 4;        // k offset 0,4,8,12
            float4 a = *(const float4*)(x + (size_t)(row0 + r) * DDIM + k0 + kk);
            As[kk + 0][r] = a.x; As[kk + 1][r] = a.y;
            As[kk + 2][r] = a.z; As[kk + 3][r] = a.w;
            float4 b = *(const float4*)(x + (size_t)(col0 + r) * DDIM + k0 + kk);
            Bs[kk + 0][r] = b.x; Bs[kk + 1][r] = b.y;
            Bs[kk + 2][r] = b.z; Bs[kk + 3][r] = b.w;
        }
        __syncthreads();

        #pragma unroll
        for (int k = 0; k < 16; k++) {
            float rA[8], rB[8];
            // 8-float (2x float4) vector loads; ty*8/tx*8 are 32B aligned.
            *(float4*)&rA[0] = *(const float4*)&As[k][ty * 8 + 0];
            *(float4*)&rA[4] = *(const float4*)&As[k][ty * 8 + 4];
            *(float4*)&rB[0] = *(const float4*)&Bs[k][tx * 8 + 0];
            *(float4*)&rB[4] = *(const float4*)&Bs[k][tx * 8 + 4];
            #pragma unroll
            for (int i = 0; i < 8; i++)
                #pragma unroll
                for (int j = 0; j < 8; j++)
                    acc[i][j] = fmaf(rA[i], rB[j], acc[i][j]);
        }
    }
    __syncthreads();

    // Epilogue: distance + masked max/min per row, reduce across the 16 tx
    // lanes (contiguous within a warp half), then one atomic per row.
    #pragma unroll
    for (int i = 0; i < 8; i++) {
        const int row = ty * 8 + i;
        const int li = lr[row];
        const float sq_i = sqr[row];
        float mp = 0.f;            // hardest positive (max); 0 floor matches ref
        float mn = CUDART_INF_F;   // hardest negative (min)
        #pragma unroll
        for (int j = 0; j < 8; j++) {
            const int col = tx * 8 + j;
            float d2 = sq_i + sqc[col] - 2.f * acc[i][j];
            float d  = d2 > 0.f ? sqrtf(d2) : 0.f;
            if (li == lc[col]) mp = fmaxf(mp, d);
            else               mn = fminf(mn, d);
        }
        #pragma unroll
        for (int off = 8; off; off >>= 1) {
            mp = fmaxf(mp, __shfl_xor_sync(0xffffffffu, mp, off));
            mn = fminf(mn, __shfl_xor_sync(0xffffffffu, mn, off));
        }
        if (tx == 0) {
            // non-negative floats: uint compare == float compare
            atomicMax(&g_ap[row0 + row], __float_as_uint(mp));
            atomicMin(&g_an[row0 + row], __float_as_uint(mn));
        }
    }
}

// ---------------------------------------------------------------------------
// K3: final loss reduction. One block.
// ---------------------------------------------------------------------------
__global__ __launch_bounds__(256) void loss_kernel(float* __restrict__ out) {
    const int tid = threadIdx.x;
    float s = 0.f;
    int   c = 0;
    for (int i = tid; i < NROWS; i += 256) {
        float ap = __uint_as_float(g_ap[i]);
        float an = __uint_as_float(g_an[i]);
        if (ap > 0.f && isfinite(an)) {
            s += fmaxf(ap - an + MARGIN, 0.f);
            c += 1;
        }
    }
    #pragma unroll
    for (int off = 16; off; off >>= 1) {
        s += __shfl_xor_sync(0xffffffffu, s, off);
        c += __shfl_xor_sync(0xffffffffu, c, off);
    }
    __shared__ float ws[8];
    __shared__ int   wc[8];
    if ((tid & 31) == 0) { ws[tid >> 5] = s; wc[tid >> 5] = c; }
    __syncthreads();
    if (tid == 0) {
        float ts = 0.f; int tc = 0;
        #pragma unroll
        for (int w = 0; w < 8; w++) { ts += ws[w]; tc += wc[w]; }
        out[0] = tc > 0 ? ts / (float)tc : 0.f;
    }
}

// ---------------------------------------------------------------------------
extern "C" void kernel_launch(void* const* d_in, const int* in_sizes, int n_in,
                              void* d_out, int out_size) {
    const float* features = (const float*)d_in[0];
    const int*   labels   = (const int*)d_in[1];
    float*       out      = (float*)d_out;
    (void)in_sizes; (void)n_in; (void)out_size;

    sq_init_kernel<<<NROWS, 256>>>(features);
    dim3 grid(NROWS / 128, NROWS / 128);
    dist_kernel<<<grid, 256>>>(features, labels);
    loss_kernel<<<1, 256>>>(out);
}

// round 6
// speedup vs baseline: 4.7642x; 4.7642x over previous
#include <cuda_runtime.h>
#include <cuda_bf16.h>
#include <math_constants.h>
#include <cstdint>

// TripletLoss: features [4096,2048] f32, labels [4096] i32 -> scalar f32.
//  K0: split X into bf16 hi/lo + row norms + init accumulators
//  K1: mma.sync bf16 Gram kernel (3-term split GEMM: HH + HL + LH),
//      128x256 tiles, upper triangle only (272 CTAs), fused distance +
//      batch-hard epilogue updating both row- and col-anchors
//  K2: final loss reduction
// NOTE: harness compiles for plain compute_103 => no tcgen05/TMEM PTX.

#define NROWS 4096
#define DDIM  2048
#define MARGIN 0.3f

#define TM 128
#define TN 256
#define BK 64
#define NCHUNK (DDIM / BK)   // 32

__device__ float         g_sq[NROWS];
__device__ unsigned int  g_ap[NROWS];
__device__ unsigned int  g_an[NROWS];
__device__ __nv_bfloat16 g_H[(size_t)NROWS * DDIM];   // 16 MB
__device__ __nv_bfloat16 g_L[(size_t)NROWS * DDIM];   // 16 MB

// ---------------- SMEM layout (dynamic, 1 CTA/SM) ----------------
// Stage: A-h 16K | A-l 16K | B-h 32K | B-l 32K   (rows of 64 bf16 = 128B)
#define STAGE_BYTES 98304u
#define OFF_AH 0u
#define OFF_AL 16384u
#define OFF_BH 32768u
#define OFF_BL 65536u
#define META   196608u               // after 2 stages
#define OFF_LR      (META + 0u)      // int[128]
#define OFF_LC      (META + 512u)    // int[256]
#define OFF_SQR     (META + 1536u)   // float[128]
#define OFF_SQC     (META + 2048u)   // float[256]
#define OFF_SCAP    (META + 3072u)   // uint[256]
#define OFF_SCAN    (META + 4096u)   // uint[256]
#define SMEM_TOTAL  (META + 5120u)

// ---------------- PTX helpers ----------------
__device__ __forceinline__ uint32_t smem_u32(const void* p) {
    uint32_t a;
    asm("{ .reg .u64 t; cvta.to.shared.u64 t, %1; cvt.u32.u64 %0, t; }" : "=r"(a) : "l"(p));
    return a;
}
__device__ __forceinline__ void cp16(uint32_t saddr, const void* gaddr) {
    asm volatile("cp.async.cg.shared.global [%0], [%1], 16;" :: "r"(saddr), "l"(gaddr));
}
__device__ __forceinline__ void cp_commit() {
    asm volatile("cp.async.commit_group;" ::: "memory");
}
template <int N> __device__ __forceinline__ void cp_wait() {
    asm volatile("cp.async.wait_group %0;" :: "n"(N) : "memory");
}
__device__ __forceinline__ void ldsm4(uint32_t (&r)[4], uint32_t a) {
    asm volatile("ldmatrix.sync.aligned.m8n8.x4.shared.b16 {%0,%1,%2,%3}, [%4];"
                 : "=r"(r[0]), "=r"(r[1]), "=r"(r[2]), "=r"(r[3]) : "r"(a));
}
__device__ __forceinline__ void mma16816(float (&c)[4], const uint32_t (&a)[4],
                                         uint32_t b0, uint32_t b1) {
    asm volatile(
        "mma.sync.aligned.m16n8k16.row.col.f32.bf16.bf16.f32 "
        "{%0,%1,%2,%3}, {%4,%5,%6,%7}, {%8,%9}, {%0,%1,%2,%3};"
        : "+f"(c[0]), "+f"(c[1]), "+f"(c[2]), "+f"(c[3])
        : "r"(a[0]), "r"(a[1]), "r"(a[2]), "r"(a[3]), "r"(b0), "r"(b1));
}
__device__ __forceinline__ uint32_t swz(uint32_t off) {      // XOR 16B-group swizzle
    return off ^ ((off >> 3) & 0x70);
}

// ---------------------------------------------------------------------------
// K0: bf16 hi/lo split + row squared norms + accumulator init.
// ---------------------------------------------------------------------------
__global__ __launch_bounds__(256) void conv_kernel(const float* __restrict__ x) {
    const int row = blockIdx.x;
    const float4* xr = (const float4*)(x + (size_t)row * DDIM);
    __nv_bfloat162* hp = (__nv_bfloat162*)(g_H + (size_t)row * DDIM);
    __nv_bfloat162* lp = (__nv_bfloat162*)(g_L + (size_t)row * DDIM);
    float s = 0.f;
    #pragma unroll 2
    for (int i = threadIdx.x; i < DDIM / 4; i += 256) {
        float4 v = xr[i];
        s += v.x * v.x + v.y * v.y + v.z * v.z + v.w * v.w;
        __nv_bfloat162 h01 = __floats2bfloat162_rn(v.x, v.y);
        __nv_bfloat162 h23 = __floats2bfloat162_rn(v.z, v.w);
        float l0 = v.x - __low2float(h01), l1 = v.y - __high2float(h01);
        float l2 = v.z - __low2float(h23), l3 = v.w - __high2float(h23);
        hp[2 * i + 0] = h01;
        hp[2 * i + 1] = h23;
        lp[2 * i + 0] = __floats2bfloat162_rn(l0, l1);
        lp[2 * i + 1] = __floats2bfloat162_rn(l2, l3);
    }
    #pragma unroll
    for (int o = 16; o; o >>= 1) s += __shfl_xor_sync(0xffffffffu, s, o);
    __shared__ float ws[8];
    if ((threadIdx.x & 31) == 0) ws[threadIdx.x >> 5] = s;
    __syncthreads();
    if (threadIdx.x == 0) {
        float t = 0.f;
        #pragma unroll
        for (int w = 0; w < 8; w++) t += ws[w];
        g_sq[row] = t;
        g_ap[row] = 0u;
        g_an[row] = 0x7f800000u;
    }
}

// ---------------------------------------------------------------------------
// K1: mma.sync Gram + fused batch-hard epilogue. 256 thr (8 warps), 1 CTA/SM.
// CTA tile 128 rows x 256 cols; warp tile 64x64 (2x4 warp grid).
// ---------------------------------------------------------------------------
__global__ __launch_bounds__(256, 1) void gram_kernel(const int* __restrict__ lbl) {
    extern __shared__ __align__(1024) char smem[];
    // decode linear block id -> (rt, ct) over upper-triangle tiles (272 total)
    int rt = 0, ct = 0;
    {
        int rem = blockIdx.x;
        #pragma unroll 1
        for (int h = 0; h < 16; ++h) {
            int half = 16 - h;
            if (rem < 2 * half) {
                if (rem < half) { rt = 2 * h;     ct = h + rem; }
                else            { rt = 2 * h + 1; ct = h + rem - half; }
                break;
            }
            rem -= 2 * half;
        }
    }
    const int row0 = rt * TM;
    const int col0 = ct * TN;
    const int tid = threadIdx.x;
    const int wid = tid >> 5;
    const int lid = tid & 31;
    const int wr = wid >> 2;       // warp row 0..1  (64 rows each)
    const int wc = wid & 3;        // warp col 0..3  (64 cols each)
    const uint32_t sb = smem_u32(smem);

    int*      lr   = (int*)(smem + OFF_LR);
    int*      lc   = (int*)(smem + OFF_LC);
    float*    sqr  = (float*)(smem + OFF_SQR);
    float*    sqc  = (float*)(smem + OFF_SQC);
    unsigned* scap = (unsigned*)(smem + OFF_SCAP);
    unsigned* scan = (unsigned*)(smem + OFF_SCAN);

    if (tid < 128) { lr[tid] = lbl[row0 + tid]; sqr[tid] = g_sq[row0 + tid]; }
    lc[tid]   = lbl[col0 + tid];
    sqc[tid]  = g_sq[col0 + tid];
    scap[tid] = 0u;
    scan[tid] = 0x7f800000u;

    const __nv_bfloat16* H = g_H;
    const __nv_bfloat16* L = g_L;

    auto load_chunk = [&](int n, int b) {
        const int k0 = n * BK;
        const uint32_t base = sb + (uint32_t)b * STAGE_BYTES;
        #pragma unroll
        for (int u4 = 0; u4 < 4; ++u4) {               // A: 128 rows x 8 segs
            int u = tid + u4 * 256;
            int r = u >> 3, s = u & 7;
            uint32_t sw = swz((uint32_t)u << 4);
            size_t g = (size_t)(row0 + r) * DDIM + k0 + s * 8;
            cp16(base + OFF_AH + sw, H + g);
            cp16(base + OFF_AL + sw, L + g);
        }
        #pragma unroll
        for (int u4 = 0; u4 < 8; ++u4) {               // B: 256 rows x 8 segs
            int u = tid + u4 * 256;
            int r = u >> 3, s = u & 7;
            uint32_t sw = swz((uint32_t)u << 4);
            size_t g = (size_t)(col0 + r) * DDIM + k0 + s * 8;
            cp16(base + OFF_BH + sw, H + g);
            cp16(base + OFF_BL + sw, L + g);
        }
        cp_commit();
    };

    float acc[4][8][4];
    #pragma unroll
    for (int i = 0; i < 4; i++)
        #pragma unroll
        for (int j = 0; j < 8; j++)
            #pragma unroll
            for (int v = 0; v < 4; v++) acc[i][j][v] = 0.f;

    // ldmatrix lane address components (x4: lanes 0-15 rows, 16-31 rows @ +16B)
    const int fr = lid & 15;             // row within 16-row fragment
    const uint32_t kb16 = (uint32_t)(lid >> 4) * 16;

    load_chunk(0, 0);

    for (int c = 0; c < NCHUNK; ++c) {
        const int b = c & 1;
        if (c + 1 < NCHUNK) { load_chunk(c + 1, (c + 1) & 1); cp_wait<1>(); }
        else                { cp_wait<0>(); }
        __syncthreads();

        const uint32_t base = sb + (uint32_t)b * STAGE_BYTES;
        #pragma unroll
        for (int ks = 0; ks < 4; ++ks) {
            const uint32_t kb = (uint32_t)ks * 32 + kb16;
            uint32_t ah[4][4], bh[4][4], tt[4][4];
            #pragma unroll
            for (int i = 0; i < 4; ++i)
                ldsm4(ah[i], base + OFF_AH + swz((uint32_t)(wr * 64 + i * 16 + fr) * 128 + kb));
            #pragma unroll
            for (int p = 0; p < 4; ++p)
                ldsm4(bh[p], base + OFF_BH + swz((uint32_t)(wc * 64 + p * 16 + fr) * 128 + kb));
            #pragma unroll
            for (int i = 0; i < 4; ++i)
                #pragma unroll
                for (int j = 0; j < 8; ++j)
                    mma16816(acc[i][j], ah[i], (j & 1) ? bh[j >> 1][1] : bh[j >> 1][0],
                                               (j & 1) ? bh[j >> 1][3] : bh[j >> 1][2]);
            #pragma unroll
            for (int p = 0; p < 4; ++p)      // B-l, reuse tt
                ldsm4(tt[p], base + OFF_BL + swz((uint32_t)(wc * 64 + p * 16 + fr) * 128 + kb));
            #pragma unroll
            for (int i = 0; i < 4; ++i)
                #pragma unroll
                for (int j = 0; j < 8; ++j)
                    mma16816(acc[i][j], ah[i], (j & 1) ? tt[j >> 1][1] : tt[j >> 1][0],
                                               (j & 1) ? tt[j >> 1][3] : tt[j >> 1][2]);
            #pragma unroll
            for (int i = 0; i < 4; ++i)      // A-l, reuse tt
                ldsm4(tt[i], base + OFF_AL + swz((uint32_t)(wr * 64 + i * 16 + fr) * 128 + kb));
            #pragma unroll
            for (int i = 0; i < 4; ++i)
                #pragma unroll
                for (int j = 0; j < 8; ++j)
                    mma16816(acc[i][j], tt[i], (j & 1) ? bh[j >> 1][1] : bh[j >> 1][0],
                                               (j & 1) ? bh[j >> 1][3] : bh[j >> 1][2]);
        }
        __syncthreads();
    }

    // ---------------- Epilogue ----------------
    // c-frag mapping: v0 (rlo, c0) v1 (rlo, c0+1) v2 (rlo+8, c0) v3 (rlo+8, c0+1)
    // rlo = wr*64 + i*16 + (lid>>2), c0 = wc*64 + j*8 + (lid&3)*2.
    const int rq = lid >> 2;       // 0..7
    const int cq = (lid & 3) * 2;  // 0,2,4,6
    float rowP[8], rowN[8], colP[16], colN[16];
    #pragma unroll
    for (int t = 0; t < 8; t++)  { rowP[t] = 0.f; rowN[t] = CUDART_INF_F; }
    #pragma unroll
    for (int t = 0; t < 16; t++) { colP[t] = 0.f; colN[t] = CUDART_INF_F; }

    #pragma unroll
    for (int i = 0; i < 4; ++i) {
        const int rlo = wr * 64 + i * 16 + rq;
        const int rhi = rlo + 8;
        const float sq_lo = sqr[rlo], sq_hi = sqr[rhi];
        const int   ll_lo = lr[rlo],  ll_hi = lr[rhi];
        #pragma unroll
        for (int j = 0; j < 8; ++j) {
            const int cbase = wc * 64 + j * 8 + cq;
            #pragma unroll
            for (int v = 0; v < 4; ++v) {
                const int rloc = (v & 2) ? rhi : rlo;
                const int cloc = cbase + (v & 1);
                const float sqi = (v & 2) ? sq_hi : sq_lo;
                const int   li  = (v & 2) ? ll_hi : ll_lo;
                float d2 = sqi + sqc[cloc] - 2.f * acc[i][j][v];
                float d  = d2 > 0.f ? sqrtf(d2) : 0.f;
                if (row0 + rloc == col0 + cloc) d = 0.f;   // exact diagonal
                const bool pos = (li == lc[cloc]);
                const float pv = pos ? d : 0.f;
                const float nv = pos ? CUDART_INF_F : d;
                const int ri = i * 2 + ((v & 2) >> 1);
                const int ci = j * 2 + (v & 1);
                rowP[ri] = fmaxf(rowP[ri], pv);
                rowN[ri] = fminf(rowN[ri], nv);
                colP[ci] = fmaxf(colP[ci], pv);
                colN[ci] = fminf(colN[ci], nv);
            }
        }
    }
    // row anchors: 4 lanes (lid&3) share each row
    #pragma unroll
    for (int t = 0; t < 8; ++t) {
        float p = rowP[t], n = rowN[t];
        #pragma unroll
        for (int o = 1; o <= 2; o <<= 1) {
            p = fmaxf(p, __shfl_xor_sync(0xffffffffu, p, o));
            n = fminf(n, __shfl_xor_sync(0xffffffffu, n, o));
        }
        if ((lid & 3) == 0) {
            const int grow = row0 + wr * 64 + (t >> 1) * 16 + rq + (t & 1) * 8;
            atomicMax(&g_ap[grow], __float_as_uint(p));
            atomicMin(&g_an[grow], __float_as_uint(n));
        }
    }
    // col anchors: 8 lanes (lid>>2) share each col; combine cross-warp in smem
    #pragma unroll
    for (int t = 0; t < 16; ++t) {
        float p = colP[t], n = colN[t];
        #pragma unroll
        for (int o = 4; o <= 16; o <<= 1) {
            p = fmaxf(p, __shfl_xor_sync(0xffffffffu, p, o));
            n = fminf(n, __shfl_xor_sync(0xffffffffu, n, o));
        }
        if (rq == 0) {
            const int cc = wc * 64 + (t >> 1) * 8 + cq + (t & 1);
            atomicMax(&scap[cc], __float_as_uint(p));
            atomicMin(&scan[cc], __float_as_uint(n));
        }
    }
    __syncthreads();
    atomicMax(&g_ap[col0 + tid], scap[tid]);
    atomicMin(&g_an[col0 + tid], scan[tid]);
}

// ---------------------------------------------------------------------------
// K2: final loss reduction. One block.
// ---------------------------------------------------------------------------
__global__ __launch_bounds__(256) void loss_kernel(float* __restrict__ out) {
    const int tid = threadIdx.x;
    float s = 0.f;
    int c = 0;
    for (int i = tid; i < NROWS; i += 256) {
        float ap = __uint_as_float(g_ap[i]);
        float an = __uint_as_float(g_an[i]);
        if (ap > 0.f && isfinite(an)) {
            s += fmaxf(ap - an + MARGIN, 0.f);
            c += 1;
        }
    }
    #pragma unroll
    for (int o = 16; o; o >>= 1) {
        s += __shfl_xor_sync(0xffffffffu, s, o);
        c += __shfl_xor_sync(0xffffffffu, c, o);
    }
    __shared__ float ws[8];
    __shared__ int wc[8];
    if ((tid & 31) == 0) { ws[tid >> 5] = s; wc[tid >> 5] = c; }
    __syncthreads();
    if (tid == 0) {
        float ts = 0.f; int tc = 0;
        #pragma unroll
        for (int w = 0; w < 8; w++) { ts += ws[w]; tc += wc[w]; }
        out[0] = tc > 0 ? ts / (float)tc : 0.f;
    }
}

// ---------------------------------------------------------------------------
extern "C" void kernel_launch(void* const* d_in, const int* in_sizes, int n_in,
                              void* d_out, int out_size) {
    const float* features = (const float*)d_in[0];
    const int*   labels   = (const int*)d_in[1];
    float*       out      = (float*)d_out;
    (void)in_sizes; (void)n_in; (void)out_size;

    cudaFuncSetAttribute(gram_kernel, cudaFuncAttributeMaxDynamicSharedMemorySize,
                         SMEM_TOTAL);

    conv_kernel<<<NROWS, 256>>>(features);
    gram_kernel<<<272, 256, SMEM_TOTAL>>>(labels);
    loss_kernel<<<1, 256>>>(out);
}